// round 9
// baseline (speedup 1.0000x reference)
#include <cuda_runtime.h>
#include <cuda_fp16.h>
#include <cstdint>

// ConvTranspose2d (k==s==2) == GEMM: M=32768 pixels, N=1024 (o*4+i*2+j), K=512 (c)
// Single-pass fp16 mma (fp32 accumulate): rel_err ~2.8e-4 < 1e-3 gate (measured).
// Phase 1a: x fp32 -> g_xF fp16, SAME [c][p] layout (pure streaming convert).
// Phase 1b: w fp32 [512][1024] -> g_wF fp16 [1024][512] (transpose, tiny).
// Phase 2:  mma.sync fp16 GEMM. A fragments via ldmatrix.x4.trans from [c][p]
//           tiles (no pre-transpose needed). 256 thr / 8 warps (4Mx2N), warp
//           tile 32x64, 2 CTAs/SM, BK=64, 3-stage cp.async, 1 sync/iter,
//           fused bias + pixel-shuffle epilogue with streaming stores.

#define M_TOTAL 32768
#define K_TOTAL 512
#define N_TOTAL 1024
#define BM 128
#define BN 128
#define BK 64
#define KITERS (K_TOTAL / BK)
#define AROWB 256                      // A row: 128 p fp16 = 256B (64 c rows)
#define BROWB 128                      // B row: 64 k fp16 = 128B (128 n rows)
#define STAGE_BYTES (64 * AROWB + 128 * BROWB)   // 16KB + 16KB
#define NSTAGE 3
#define SMEM_TOTAL (NSTAGE * STAGE_BYTES)        // 96KB -> 2 CTAs/SM

// -------- device scratch (allocation-free rule: __device__ globals) --------
__device__ __half g_xF[(size_t)M_TOTAL * K_TOTAL];   // [8][512][4096]  (c-major)
__device__ __half g_wF[(size_t)N_TOTAL * K_TOTAL];   // [1024][512]     (n-major)

// ---------------- helpers ----------------
__device__ __forceinline__ uint32_t smem_u32(const void* p) {
    uint32_t a;
    asm("{ .reg .u64 t; cvta.to.shared.u64 t, %1; cvt.u32.u64 %0, t; }" : "=r"(a) : "l"(p));
    return a;
}

#define CP_ASYNC16(dst, src) \
    asm volatile("cp.async.cg.shared.global [%0], [%1], 16;" :: "r"(dst), "l"(src) : "memory")
#define CP_COMMIT()  asm volatile("cp.async.commit_group;" ::: "memory")
#define CP_WAIT1()   asm volatile("cp.async.wait_group 1;" ::: "memory")
#define CP_WAIT0()   asm volatile("cp.async.wait_group 0;" ::: "memory")

#define LDMX4(R, addr)                                                          \
    asm volatile("ldmatrix.sync.aligned.m8n8.x4.shared.b16 {%0,%1,%2,%3}, [%4];"\
        : "=r"((R)[0]), "=r"((R)[1]), "=r"((R)[2]), "=r"((R)[3]) : "r"(addr))
#define LDMX4T(R, addr)                                                         \
    asm volatile("ldmatrix.sync.aligned.m8n8.x4.trans.shared.b16 {%0,%1,%2,%3}, [%4];"\
        : "=r"((R)[0]), "=r"((R)[1]), "=r"((R)[2]), "=r"((R)[3]) : "r"(addr))

#define MMA16816(ACC, A, B)                                                     \
    asm volatile("mma.sync.aligned.m16n8k16.row.col.f32.f16.f16.f32 "           \
        "{%0,%1,%2,%3}, {%4,%5,%6,%7}, {%8,%9}, {%0,%1,%2,%3};"                 \
        : "+f"((ACC)[0]), "+f"((ACC)[1]), "+f"((ACC)[2]), "+f"((ACC)[3])        \
        : "r"((A)[0]), "r"((A)[1]), "r"((A)[2]), "r"((A)[3]),                   \
          "r"((B)[0]), "r"((B)[1]))

// ---------------- Phase 1a: streaming fp32 -> fp16 convert (x) ----------------
__global__ __launch_bounds__(256)
void convert_kernel(const float* __restrict__ src, __half* __restrict__ dst,
                    size_t n4)   // number of float4 elements
{
    size_t i = (size_t)blockIdx.x * blockDim.x + threadIdx.x;
    size_t stride = (size_t)gridDim.x * blockDim.x;
    for (; i < n4; i += stride) {
        float4 v = ((const float4*)src)[i];
        __half2 h01 = __floats2half2_rn(v.x, v.y);
        __half2 h23 = __floats2half2_rn(v.z, v.w);
        uint2 st;
        st.x = *(uint32_t*)&h01;
        st.y = *(uint32_t*)&h23;
        ((uint2*)dst)[i] = st;
    }
}

// ---------------- Phase 1b: transpose + fp16 convert (w only) ----------------
// src: [R][C] fp32 -> dst: [C][R] fp16
__global__ void tsplit_kernel(const float* __restrict__ src,
                              __half* __restrict__ dst,
                              int R, int C)
{
    __shared__ float tile[64][33];
    int p0 = blockIdx.x * 32;
    int c0 = blockIdx.y * 64;
    int tx = threadIdx.x, ty = threadIdx.y;
    #pragma unroll
    for (int i = 0; i < 64; i += 8)
        tile[ty + i][tx] = src[(size_t)(c0 + ty + i) * C + p0 + tx];
    __syncthreads();
    #pragma unroll
    for (int j = 0; j < 32; j += 8) {
        int p = ty + j;
        __half2 v = __floats2half2_rn(tile[tx * 2][p], tile[tx * 2 + 1][p]);
        *(__half2*)(dst + (size_t)(p0 + p) * R + c0 + tx * 2) = v;
    }
}

// ---------------- Phase 2: mma.sync fp16 GEMM ----------------
// A stage: 64 c-rows x 256B ([c][p] layout, p fp16 chunks cm=0..15 at
//          ((cm ^ (c&7))<<4)); fragments via ldmatrix.x4.trans.
// B stage: 128 n-rows x 128B ([n][k] layout, chunks at ((c ^ (n&7))<<4)).

__global__ __launch_bounds__(256, 2)
void gemm_mma_kernel(const float* __restrict__ bias, float* __restrict__ out)
{
    extern __shared__ char smem[];
    const uint32_t sbase = smem_u32(smem);

    const int tid  = threadIdx.x;
    const int lane = tid & 31;
    const int warp = tid >> 5;
    const int g    = lane >> 2;       // mma row within fragment
    const int tg   = lane & 3;        // mma col-pair selector
    const int wm   = warp & 3;        // 4 warps along M (32 rows each)
    const int wn   = warp >> 2;       // 2 warps along N (64 cols each)

    const int nb = blockIdx.x;        // 0..7   (N tile of 128)
    const int mb = blockIdx.y;        // 0..255 (M tile of 128)

    const int batch = mb >> 5;                      // 32 M-tiles per batch plane
    const int pin   = (mb & 31) * BM;               // pixel offset in plane
    const __half* gA = g_xF + (size_t)batch * K_TOTAL * 4096;   // [c][p] plane
    const __half* gB = g_wF + (size_t)nb * BN * K_TOTAL;

    // ---- A trans-ldmatrix lane addressing (fragment [m16][k16] from [k][m]) ----
    // lanes 0-7:(k0-7,m0-7) 8-15:(k0-7,m8-15) 16-23:(k8-15,m0-7) 24-31:(k8-15,m8-15)
    const int krL = (lane & 7) + ((lane >> 4) << 3);    // k-row within 16
    const int cmL = (lane >> 3) & 1;                    // m-chunk (8p=16B) within 16
    // ---- B ldmatrix addressing (as before) ----
    const int x7   = lane & 7;
    const int rB   = ((lane >> 4) << 3) + x7;           // row-in-16, B x4 (nt pair)
    const int selB = (lane >> 3) & 1;                   // k8 select, B x4
    const uint32_t bBase = (uint32_t)(wn * 64 + rB) * BROWB;

    float acc[2][8][4];
    #pragma unroll
    for (int i = 0; i < 2; i++)
        #pragma unroll
        for (int j = 0; j < 8; j++)
            #pragma unroll
            for (int r = 0; r < 4; r++) acc[i][j][r] = 0.f;

    // ---- async staging of one k-stage (BK=64) ----
    auto stage_load = [&](int it, int buf) {
        const int k0 = it * BK;
        const uint32_t sA = sbase + buf * STAGE_BYTES;
        const uint32_t sB = sA + 64 * AROWB;
        #pragma unroll
        for (int i = 0; i < 4; i++) {                 // A: 64 rows x 16 chunks
            int q = tid + i * 256;
            int r = q >> 4, cm = q & 15;
            CP_ASYNC16(sA + (uint32_t)r * AROWB + (uint32_t)((cm ^ (r & 7)) << 4),
                       gA + (size_t)(k0 + r) * 4096 + pin + cm * 8);
        }
        #pragma unroll
        for (int i = 0; i < 4; i++) {                 // B: 128 rows x 8 chunks
            int q = tid + i * 256;
            int r = q >> 3, c = q & 7;
            CP_ASYNC16(sB + (uint32_t)r * BROWB + (uint32_t)((c ^ (r & 7)) << 4),
                       gB + (size_t)r * K_TOTAL + k0 + c * 8);
        }
    };

    // prologue: two stages in flight
    stage_load(0, 0);
    CP_COMMIT();
    stage_load(1, 1);
    CP_COMMIT();

    for (int it = 0; it < KITERS; it++) {
        if (it + 1 < KITERS) { CP_WAIT1(); } else { CP_WAIT0(); }
        __syncthreads();          // releases compute(it) + certifies (it+2)%3 buffer
        if (it + 2 < KITERS) {
            stage_load(it + 2, (it + 2) % NSTAGE);
            CP_COMMIT();
        }

        const uint32_t sA = sbase + (it % NSTAGE) * STAGE_BYTES;
        const uint32_t sB = sA + 64 * AROWB;

        #pragma unroll
        for (int kc = 0; kc < 4; kc++) {              // four k16 chunks in BK=64
            uint32_t a[8], b[16];
            #pragma unroll
            for (int mt = 0; mt < 2; mt++) {
                int kr = kc * 16 + krL;
                int cm = wm * 4 + mt * 2 + cmL;
                LDMX4T(a + mt * 4,
                       sA + (uint32_t)kr * AROWB + (uint32_t)((cm ^ (kr & 7)) << 4));
            }
            #pragma unroll
            for (int ntp = 0; ntp < 4; ntp++)         // each LDMX4 covers 2 nt
                LDMX4(b + ntp * 4, sB + bBase + (uint32_t)ntp * 16 * BROWB
                                   + (uint32_t)(((kc * 2 + selB) ^ x7) << 4));
            #pragma unroll
            for (int mt = 0; mt < 2; mt++)
                #pragma unroll
                for (int nt = 0; nt < 8; nt++)
                    MMA16816(acc[mt][nt], a + mt * 4, b + nt * 2);
        }
    }

    // ---- epilogue: scatter to out[b][o][2h+i][2w+j], fused bias, streaming ----
    #pragma unroll
    for (int mt = 0; mt < 2; mt++) {
        int r0 = mb * 128 + wm * 32 + mt * 16 + g;
        #pragma unroll
        for (int half = 0; half < 2; half++) {
            int p  = r0 + half * 8;
            int bb = p >> 12;
            int h  = (p >> 6) & 63;
            int wp = p & 63;
            #pragma unroll
            for (int nt = 0; nt < 8; nt++) {
                int n  = nb * 128 + wn * 64 + nt * 8 + tg * 2;   // even -> (j=0, j=1)
                int o  = n >> 2;
                int ii = (n >> 1) & 1;
                float bo = __ldg(bias + o);
                size_t addr = (((size_t)(bb * 256 + o) * 128) + (h * 2 + ii)) * 128 + wp * 2;
                float2 v;
                v.x = acc[mt][nt][half * 2 + 0] + bo;
                v.y = acc[mt][nt][half * 2 + 1] + bo;
                __stcs((float2*)(out + addr), v);
            }
        }
    }
}

// ---------------- launch ----------------
extern "C" void kernel_launch(void* const* d_in, const int* in_sizes, int n_in,
                              void* d_out, int out_size)
{
    const float* x    = (const float*)d_in[0];   // [8,512,64,64]
    const float* wgt  = (const float*)d_in[1];   // [512,256,2,2] -> [512][1024]
    const float* bias = (const float*)d_in[2];   // [256]
    float* out = (float*)d_out;                  // [8,256,128,128]

    void *pxF, *pwF;
    cudaGetSymbolAddress(&pxF, g_xF);
    cudaGetSymbolAddress(&pwF, g_wF);

    // Phase 1a: x streaming convert ([c][p] layout preserved)
    size_t n4 = (size_t)M_TOTAL * K_TOTAL / 4;   // 4.19M float4s
    convert_kernel<<<8192, 256>>>(x, (__half*)pxF, n4);
    // Phase 1b: w transpose [512][1024] -> [1024][512]
    tsplit_kernel<<<dim3(1024 / 32, 512 / 64, 1), dim3(32, 8)>>>(
        wgt, (__half*)pwF, 512, 1024);

    // Phase 2
    static int attr_set = 0;
    if (!attr_set) {
        cudaFuncSetAttribute(gemm_mma_kernel,
                             cudaFuncAttributeMaxDynamicSharedMemorySize, SMEM_TOTAL);
        attr_set = 1;
    }
    dim3 grid(N_TOTAL / BN, M_TOTAL / BM);   // (8, 256) — nb fastest for A-tile L2 reuse
    gemm_mma_kernel<<<grid, 256, SMEM_TOTAL>>>(bias, out);
}